// round 7
// baseline (speedup 1.0000x reference)
#include <cuda_runtime.h>
#include <cuda_bf16.h>

// AUCM loss, 2-kernel graph. Kernel boundary replaces software grid barrier.
// loss = [ sum_{P x N} (1-p+n)^2 + relu(1-p+n) ] / (|P||N|)
// K1: compact positives+negatives, per-block fp64 sums (S1,S2,Sp1,Sp2).
// K2: relu pairwise (positives in registers, negatives broadcast LDS),
//     last-block finalize adds closed-form quadratic term.

#define K1B     32
#define THREADS 512
#define NBLOCKS 148
#define PVEC    5              // positives per thread-group slot
#define PGROUPS 256            // thread-groups per block (tid & 255)
#define MAXPOS  4096
#define MAXN    16384
#define PADV    1.0e30f        // padded positive -> relu term 0

__device__ float  g_pos[MAXN];
__device__ float  g_neg[MAXN];
__device__ int    g_cnt  = 0;    // positives counter (reset at finalize)
__device__ int    g_ncnt = 0;    // negatives counter (reset at finalize)
__device__ int    g_done = 0;    // finalize election (reset at finalize)
__device__ double g_s1[K1B], g_s2[K1B], g_sp1[K1B], g_sp2[K1B];
__device__ double g_relu[NBLOCKS];

__device__ __forceinline__ double block_reduce(double v, double* s_w) {
    int lane = threadIdx.x & 31, wid = threadIdx.x >> 5;
    #pragma unroll
    for (int o = 16; o; o >>= 1) v += __shfl_down_sync(0xffffffffu, v, o);
    if (lane == 0) s_w[wid] = v;
    __syncthreads();
    double r = 0.0;
    if (wid == 0) {
        r = (lane < THREADS / 32) ? s_w[lane] : 0.0;
        #pragma unroll
        for (int o = 8; o; o >>= 1) r += __shfl_down_sync(0xffffffffu, r, o);
    }
    __syncthreads();
    return r;
}

// ---- Kernel 1: compaction + class sums -------------------------------------
__global__ void __launch_bounds__(THREADS)
k1_compact(const float* __restrict__ preds,
           const int* __restrict__ targets, int n) {
    __shared__ double s_w[THREADS / 32];
    const int tid  = threadIdx.x;
    const int bid  = blockIdx.x;
    const int lane = tid & 31;
    const unsigned lt_mask = (1u << lane) - 1u;

    double s1 = 0.0, s2 = 0.0, sp1 = 0.0, sp2 = 0.0;
    for (int i = bid * THREADS + tid; i < n; i += K1B * THREADS) {
        int   t = targets[i];
        float v = preds[i];
        double dv = (double)v;
        s1 += dv; s2 += dv * dv;
        bool isP = (t == 1);
        if (isP) { sp1 += dv; sp2 += dv * dv; }
        unsigned mp = __ballot_sync(0xffffffffu, isP);
        unsigned mn = ~mp;
        int basep = 0, basen = 0;
        if (lane == 0) {
            if (mp) basep = atomicAdd(&g_cnt,  __popc(mp));
            if (mn) basen = atomicAdd(&g_ncnt, __popc(mn));
        }
        basep = __shfl_sync(0xffffffffu, basep, 0);
        basen = __shfl_sync(0xffffffffu, basen, 0);
        if (isP) g_pos[basep + __popc(mp & lt_mask)] = v;
        else     g_neg[basen + __popc(mn & lt_mask)] = v;
    }
    double bs1  = block_reduce(s1,  s_w);
    double bs2  = block_reduce(s2,  s_w);
    double bsp1 = block_reduce(sp1, s_w);
    double bsp2 = block_reduce(sp2, s_w);
    if (tid == 0) {
        g_s1[bid] = bs1;  g_s2[bid] = bs2;
        g_sp1[bid] = bsp1; g_sp2[bid] = bsp2;
    }
}

// ---- Kernel 2: relu pairwise + finalize ------------------------------------
__global__ void __launch_bounds__(THREADS)
k2_pairwise(int n, float* __restrict__ out, int out_size) {
    __shared__ float  s_neg[256];
    __shared__ int    s_last;
    __shared__ double s_w[THREADS / 32];

    const int tid = threadIdx.x;
    const int bid = blockIdx.x;
    if (tid == 0) s_last = 0;

    const int pcount = g_cnt;
    const int ncount = g_ncnt;

    // Stage this block's negative chunk into shared.
    const int NC = (ncount + NBLOCKS - 1) / NBLOCKS;      // <=111 for n=16384
    const int j0 = bid * NC;
    const int j1 = min(j0 + NC, ncount);
    const int nc = max(j1 - j0, 0);
    for (int k = tid; k < nc; k += THREADS) s_neg[k] = g_neg[j0 + k];
    __syncthreads();

    // Thread = (pgroup g, half h). Positives live in registers.
    const int g = tid & (PGROUPS - 1);
    const int h = tid >> 8;                               // 0 or 1
    const int jh0 = h * (nc >> 1);
    const int jh1 = (h == 0) ? (nc >> 1) : nc;

    double dacc = 0.0;
    for (int gb = g; gb * PVEC < pcount; gb += PGROUPS) { // 1 iter if pcount<=1280
        int pb = gb * PVEC;
        float p0 = (pb + 0 < pcount) ? g_pos[pb + 0] : PADV;
        float p1 = (pb + 1 < pcount) ? g_pos[pb + 1] : PADV;
        float p2 = (pb + 2 < pcount) ? g_pos[pb + 2] : PADV;
        float p3 = (pb + 3 < pcount) ? g_pos[pb + 3] : PADV;
        float p4 = (pb + 4 < pcount) ? g_pos[pb + 4] : PADV;

        float a0 = 0.f, a1 = 0.f;
        for (int j = jh0; j < jh1; ++j) {
            float c = 1.0f + s_neg[j];        // broadcast LDS
            a0 += fmaxf(c - p0, 0.f);
            a1 += fmaxf(c - p1, 0.f);
            a0 += fmaxf(c - p2, 0.f);
            a1 += fmaxf(c - p3, 0.f);
            a0 += fmaxf(c - p4, 0.f);
        }
        dacc += (double)(a0 + a1);
    }
    double brelu = block_reduce(dacc, s_w);

    // Publish per-block partial, elect last block.
    if (tid == 0) {
        g_relu[bid] = brelu;
        __threadfence();
        int prev = atomicAdd(&g_done, 1);
        if (prev == NBLOCKS - 1) s_last = 1;
    }
    __syncthreads();

    if (s_last) {
        __threadfence();
        double vr = (tid < NBLOCKS) ? g_relu[tid] : 0.0;
        double v1 = (tid < K1B) ? g_s1[tid]  : 0.0;
        double v2 = (tid < K1B) ? g_s2[tid]  : 0.0;
        double v3 = (tid < K1B) ? g_sp1[tid] : 0.0;
        double v4 = (tid < K1B) ? g_sp2[tid] : 0.0;
        double relu_sum = block_reduce(vr, s_w);
        double S1  = block_reduce(v1, s_w);
        double S2  = block_reduce(v2, s_w);
        double Sp1 = block_reduce(v3, s_w);
        double Sp2 = block_reduce(v4, s_w);

        if (tid == 0) {
            double Np = (double)pcount, Nn = (double)(n - pcount);
            double sa  = Np - Sp1;                    // sum (1-p)
            double sa2 = Np - 2.0 * Sp1 + Sp2;        // sum (1-p)^2
            double sn  = S1 - Sp1;                    // sum n
            double sn2 = S2 - Sp2;                    // sum n^2
            double quad = Nn * sa2 + 2.0 * sa * sn + Np * sn2;
            float r = (float)((relu_sum + quad) / (Np * Nn));
            for (int j = 0; j < out_size; j++) out[j] = r;
            g_cnt = 0; g_ncnt = 0; g_done = 0;        // restore for replay
        }
    }
}

extern "C" void kernel_launch(void* const* d_in, const int* in_sizes, int n_in,
                              void* d_out, int out_size) {
    const float* preds   = (const float*)d_in[0];
    const int*   targets = (const int*)d_in[1];
    int n = in_sizes[0];
    k1_compact<<<K1B, THREADS>>>(preds, targets, n);
    k2_pairwise<<<NBLOCKS, THREADS>>>(n, (float*)d_out, out_size);
}

// round 8
// speedup vs baseline: 1.2301x; 1.2301x over previous
#include <cuda_runtime.h>
#include <cuda_bf16.h>

// AUCM loss, 2-kernel graph.
// loss = [ sum_{P x N} (1-p+n)^2 + relu(1-p+n) ] / (|P||N|)
// K1: compact positives+negatives, per-block fp64 sums (S1,S2,Sp1,Sp2).
// K2: relu pairwise, R1-proven structure: thread = one negative, positive
//     slice staged in SHARED, 8-wide unrolled loop. Last-block finalize
//     adds the closed-form quadratic term and resets counters.

#define K1B      64
#define K1T      256
#define K2X      64            // x-blocks over negatives (64*256 = 16384 >= ncount)
#define PS       4             // positive slices (grid.y)
#define K2T      256
#define NB2      (K2X * PS)    // 256 blocks in K2
#define MAXTILE  4096

__device__ float  g_pos[16384];
__device__ float  g_neg[16384];
__device__ int    g_cnt  = 0;    // positives counter (reset at finalize)
__device__ int    g_ncnt = 0;    // negatives counter (reset at finalize)
__device__ int    g_done = 0;    // finalize election  (reset at finalize)
__device__ double g_s1[K1B], g_s2[K1B], g_sp1[K1B], g_sp2[K1B];
__device__ double g_relu[NB2];

template <int T>
__device__ __forceinline__ double block_reduce(double v, double* s_w) {
    int lane = threadIdx.x & 31, wid = threadIdx.x >> 5;
    #pragma unroll
    for (int o = 16; o; o >>= 1) v += __shfl_down_sync(0xffffffffu, v, o);
    if (lane == 0) s_w[wid] = v;
    __syncthreads();
    double r = 0.0;
    if (wid == 0) {
        r = (lane < T / 32) ? s_w[lane] : 0.0;
        #pragma unroll
        for (int o = (T / 32) / 2; o; o >>= 1)
            r += __shfl_down_sync(0xffffffffu, r, o);
    }
    __syncthreads();
    return r;
}

// ---- Kernel 1: compaction + class sums -------------------------------------
__global__ void __launch_bounds__(K1T)
k1_compact(const float* __restrict__ preds,
           const int* __restrict__ targets, int n) {
    __shared__ double s_w[K1T / 32];
    const int tid  = threadIdx.x;
    const int bid  = blockIdx.x;
    const int lane = tid & 31;
    const unsigned lt_mask = (1u << lane) - 1u;

    double s1 = 0.0, s2 = 0.0, sp1 = 0.0, sp2 = 0.0;
    for (int i = bid * K1T + tid; i < n; i += K1B * K1T) {
        int   t = targets[i];
        float v = preds[i];
        double dv = (double)v;
        s1 += dv; s2 += dv * dv;
        bool isP = (t == 1);
        if (isP) { sp1 += dv; sp2 += dv * dv; }
        unsigned mp = __ballot_sync(0xffffffffu, isP);
        unsigned mn = ~mp;
        int basep = 0, basen = 0;
        if (lane == 0) {
            if (mp) basep = atomicAdd(&g_cnt,  __popc(mp));
            if (mn) basen = atomicAdd(&g_ncnt, __popc(mn));
        }
        basep = __shfl_sync(0xffffffffu, basep, 0);
        basen = __shfl_sync(0xffffffffu, basen, 0);
        if (isP) g_pos[basep + __popc(mp & lt_mask)] = v;
        else     g_neg[basen + __popc(mn & lt_mask)] = v;
    }
    double bs1  = block_reduce<K1T>(s1,  s_w);
    double bs2  = block_reduce<K1T>(s2,  s_w);
    double bsp1 = block_reduce<K1T>(sp1, s_w);
    double bsp2 = block_reduce<K1T>(sp2, s_w);
    if (tid == 0) {
        g_s1[bid]  = bs1;  g_s2[bid]  = bs2;
        g_sp1[bid] = bsp1; g_sp2[bid] = bsp2;
    }
}

// ---- Kernel 2: relu pairwise (R1 structure) + finalize ---------------------
__global__ void __launch_bounds__(K2T)
k2_pairwise(int n, float* __restrict__ out, int out_size) {
    __shared__ float  s_pos[MAXTILE];
    __shared__ int    s_last;
    __shared__ double s_w[K2T / 32];

    const int tid = threadIdx.x;
    if (tid == 0) s_last = 0;

    const int pcount = g_cnt;
    const int ncount = g_ncnt;

    // Positive slice for this block row.
    const int per = (pcount + PS - 1) / PS;
    const int p0  = blockIdx.y * per;
    const int p1  = min(p0 + per, pcount);
    const int m   = max(p1 - p0, 0);       // <= per <= MAXTILE

    for (int k = tid; k < m; k += K2T) s_pos[k] = g_pos[p0 + k];
    __syncthreads();

    // Thread = one negative.
    const int i = blockIdx.x * K2T + tid;
    float a0 = 0.f, a1 = 0.f, a2 = 0.f, a3 = 0.f;
    float a4 = 0.f, a5 = 0.f, a6 = 0.f, a7 = 0.f;
    if (i < ncount) {
        const float c = 1.0f + g_neg[i];   // d = c - p
        int k = 0;
        for (; k + 8 <= m; k += 8) {
            a0 += fmaxf(c - s_pos[k],     0.f);
            a1 += fmaxf(c - s_pos[k + 1], 0.f);
            a2 += fmaxf(c - s_pos[k + 2], 0.f);
            a3 += fmaxf(c - s_pos[k + 3], 0.f);
            a4 += fmaxf(c - s_pos[k + 4], 0.f);
            a5 += fmaxf(c - s_pos[k + 5], 0.f);
            a6 += fmaxf(c - s_pos[k + 6], 0.f);
            a7 += fmaxf(c - s_pos[k + 7], 0.f);
        }
        for (; k < m; k++) a0 += fmaxf(c - s_pos[k], 0.f);
    }
    double dacc = (double)(((a0 + a1) + (a2 + a3)) + ((a4 + a5) + (a6 + a7)));
    double brelu = block_reduce<K2T>(dacc, s_w);

    // Publish per-block partial, elect last block (across both waves).
    const int bflat = blockIdx.y * gridDim.x + blockIdx.x;
    if (tid == 0) {
        g_relu[bflat] = brelu;
        __threadfence();
        int prev = atomicAdd(&g_done, 1);
        if (prev == NB2 - 1) s_last = 1;
    }
    __syncthreads();

    if (s_last) {
        __threadfence();
        double vr = (tid < NB2) ? g_relu[tid] : 0.0;
        double v1 = (tid < K1B) ? g_s1[tid]  : 0.0;
        double v2 = (tid < K1B) ? g_s2[tid]  : 0.0;
        double v3 = (tid < K1B) ? g_sp1[tid] : 0.0;
        double v4 = (tid < K1B) ? g_sp2[tid] : 0.0;
        double relu_sum = block_reduce<K2T>(vr, s_w);
        double S1  = block_reduce<K2T>(v1, s_w);
        double S2  = block_reduce<K2T>(v2, s_w);
        double Sp1 = block_reduce<K2T>(v3, s_w);
        double Sp2 = block_reduce<K2T>(v4, s_w);

        if (tid == 0) {
            double Np = (double)pcount, Nn = (double)(n - pcount);
            double sa  = Np - Sp1;                    // sum (1-p)
            double sa2 = Np - 2.0 * Sp1 + Sp2;        // sum (1-p)^2
            double sn  = S1 - Sp1;                    // sum n
            double sn2 = S2 - Sp2;                    // sum n^2
            double quad = Nn * sa2 + 2.0 * sa * sn + Np * sn2;
            float r = (float)((relu_sum + quad) / (Np * Nn));
            for (int j = 0; j < out_size; j++) out[j] = r;
            g_cnt = 0; g_ncnt = 0; g_done = 0;        // restore for replay
        }
    }
}

extern "C" void kernel_launch(void* const* d_in, const int* in_sizes, int n_in,
                              void* d_out, int out_size) {
    const float* preds   = (const float*)d_in[0];
    const int*   targets = (const int*)d_in[1];
    int n = in_sizes[0];
    k1_compact<<<K1B, K1T>>>(preds, targets, n);
    dim3 g2(K2X, PS);
    k2_pairwise<<<g2, K2T>>>(n, (float*)d_out, out_size);
}